// round 1
// baseline (speedup 1.0000x reference)
#include <cuda_runtime.h>
#include <cuda_bf16.h>

#define B_   64
#define NN_  64
#define HL_  50
#define IN_  384
#define POS_ 64
#define ATT_ 256
#define NEWS_ 448
#define W1COLS_ 896   // 2*NEWS

// Scratch (device globals; no allocation allowed)
__device__ float g_lf[B_ * HL_ * NEWS_];   // 1,433,600
__device__ float g_pn[B_ * NN_ * ATT_];    // 1,048,576  (includes b1 + pos part)
__device__ float g_pl[B_ * HL_ * ATT_];    //   819,200  (includes pos part)
__device__ float g_cn[ATT_];
__device__ float g_cl[HL_ * ATT_];

__device__ __forceinline__ float tanh_fast(float x) {
    float y;
    asm("tanh.approx.f32 %0, %1;" : "=f"(y) : "f"(x));
    return y;
}

// ---------------------------------------------------------------------------
// Kernel 1: build nf (-> d_out second half) and lf (-> g_lf)
// nf[b,n,:] = concat(news_vec[b,n,:], pos_emb[0,:])
// lf[b,h,:] = concat(log_vec[b,h,:],  pos_emb[1+h,:])
// ---------------------------------------------------------------------------
__global__ __launch_bounds__(256) void setup_kernel(
    const float* __restrict__ log_vec,
    const float* __restrict__ news_vec,
    const float* __restrict__ pos_emb,
    float* __restrict__ nf_out)
{
    const int NF_TOTAL = B_ * NN_ * NEWS_;
    const int LF_TOTAL = B_ * HL_ * NEWS_;
    int idx = blockIdx.x * 256 + threadIdx.x;
    if (idx < NF_TOTAL) {
        int d = idx % NEWS_;
        int r = idx / NEWS_;            // b*NN + n
        nf_out[idx] = (d < IN_) ? news_vec[r * IN_ + d] : pos_emb[d - IN_];
    } else if (idx < NF_TOTAL + LF_TOTAL) {
        int j = idx - NF_TOTAL;
        int d = j % NEWS_;
        int r = j / NEWS_;              // b*HL + h
        int h = r % HL_;
        g_lf[j] = (d < IN_) ? log_vec[r * IN_ + d]
                            : pos_emb[(1 + h) * POS_ + (d - IN_)];
    }
}

// ---------------------------------------------------------------------------
// Kernel 2: cn[a] = b1[a] + pos_emb[0] . Wn_pos[a,:]   (Wn pos cols = W1[:,384:448])
//           cl[h,a] =        pos_emb[1+h] . Wl_pos[a,:] (Wl pos cols = W1[:,832:896])
// ---------------------------------------------------------------------------
__global__ __launch_bounds__(256) void cncl_kernel(
    const float* __restrict__ pos_emb,
    const float* __restrict__ W1,
    const float* __restrict__ b1)
{
    int a = threadIdx.x;
    int blk = blockIdx.x;
    if (blk == 0) {
        float s = b1[a];
        const float* w = W1 + a * W1COLS_ + IN_;       // cols 384..447
        #pragma unroll 8
        for (int p = 0; p < POS_; p++) s += pos_emb[p] * w[p];
        g_cn[a] = s;
    } else {
        int h = blk - 1;
        float s = 0.f;
        const float* w  = W1 + a * W1COLS_ + NEWS_ + IN_;  // cols 832..895
        const float* pe = pos_emb + (1 + h) * POS_;
        #pragma unroll 8
        for (int p = 0; p < POS_; p++) s += pe[p] * w[p];
        g_cl[h * ATT_ + a] = s;
    }
}

// ---------------------------------------------------------------------------
// Kernel 3: SGEMM  C[m,a] = sum_k A[m,k] * W1[a, w_off + k]  + bias
//   mode 0: A=news_vec, M=4096, w_off=0,   C=g_pn, bias=cn[a]
//   mode 1: A=log_vec,  M=3200, w_off=448, C=g_pl, bias=cl[m%50, a]
// BM=BN=64, BK=16, 256 threads, 4x4 microtile.
// ---------------------------------------------------------------------------
#define BM 64
#define BN 64
#define BK 16
__global__ __launch_bounds__(256) void gemm_kernel(
    const float* __restrict__ A,
    const float* __restrict__ W1,
    int w_off, int mode)
{
    __shared__ float As[BK][BM];
    __shared__ float Ws[BK][BN];

    int tid = threadIdx.x;
    int bm = blockIdx.y, bn = blockIdx.x;

    int lrow = tid >> 2;          // 0..63
    int lk4  = (tid & 3) << 2;    // 0,4,8,12
    const float* Aptr = A  + (size_t)(bm * BM + lrow) * IN_    + lk4;
    const float* Wptr = W1 + (size_t)(bn * BN + lrow) * W1COLS_ + w_off + lk4;

    int tx = tid & 15, ty = tid >> 4;
    float acc[4][4] = {};

    for (int k0 = 0; k0 < IN_; k0 += BK) {
        float4 av = *(const float4*)(Aptr + k0);
        float4 wv = *(const float4*)(Wptr + k0);
        As[lk4 + 0][lrow] = av.x; As[lk4 + 1][lrow] = av.y;
        As[lk4 + 2][lrow] = av.z; As[lk4 + 3][lrow] = av.w;
        Ws[lk4 + 0][lrow] = wv.x; Ws[lk4 + 1][lrow] = wv.y;
        Ws[lk4 + 2][lrow] = wv.z; Ws[lk4 + 3][lrow] = wv.w;
        __syncthreads();
        #pragma unroll
        for (int k = 0; k < BK; k++) {
            float4 a4 = *(const float4*)&As[k][ty * 4];
            float4 b4 = *(const float4*)&Ws[k][tx * 4];
            acc[0][0] += a4.x * b4.x; acc[0][1] += a4.x * b4.y;
            acc[0][2] += a4.x * b4.z; acc[0][3] += a4.x * b4.w;
            acc[1][0] += a4.y * b4.x; acc[1][1] += a4.y * b4.y;
            acc[1][2] += a4.y * b4.z; acc[1][3] += a4.y * b4.w;
            acc[2][0] += a4.z * b4.x; acc[2][1] += a4.z * b4.y;
            acc[2][2] += a4.z * b4.z; acc[2][3] += a4.z * b4.w;
            acc[3][0] += a4.w * b4.x; acc[3][1] += a4.w * b4.y;
            acc[3][2] += a4.w * b4.z; acc[3][3] += a4.w * b4.w;
        }
        __syncthreads();
    }

    int mbase = bm * BM + ty * 4;
    int abase = bn * BN + tx * 4;
    #pragma unroll
    for (int i = 0; i < 4; i++) {
        int m = mbase + i;
        #pragma unroll
        for (int j = 0; j < 4; j++) {
            int a = abase + j;
            if (mode == 0) {
                g_pn[(size_t)m * ATT_ + a] = acc[i][j] + g_cn[a];
            } else {
                g_pl[(size_t)m * ATT_ + a] = acc[i][j] + g_cl[(m % HL_) * ATT_ + a];
            }
        }
    }
}

// ---------------------------------------------------------------------------
// Kernel 4: fused tanh-attn core. One block per (b,n), 256 threads.
// logits[h] = sum_a tanh(pn[b,n,a] + pl[b,h,a]) * W2[a] + b2 ; mask ; softmax
// out[b,n,d] = sum_h attn[h] * lf[b,h,d]
// ---------------------------------------------------------------------------
__global__ __launch_bounds__(256) void core_kernel(
    const int*   __restrict__ log_mask,
    const float* __restrict__ W2,
    const float* __restrict__ b2,
    float* __restrict__ out)
{
    __shared__ float pn_s[ATT_];
    __shared__ float w2_s[ATT_];
    __shared__ float logit_s[64];

    int bn = blockIdx.x;          // b*NN + n
    int b  = bn / NN_;
    int tid = threadIdx.x;

    pn_s[tid] = g_pn[(size_t)bn * ATT_ + tid];
    w2_s[tid] = W2[tid];
    __syncthreads();

    int warp = tid >> 5, lane = tid & 31;
    float bias2 = b2[0];

    for (int h = warp; h < HL_; h += 8) {
        const float* plrow = g_pl + (size_t)(b * HL_ + h) * ATT_;
        float s = 0.f;
        #pragma unroll
        for (int j = 0; j < 8; j++) {
            int a = lane + 32 * j;
            s += tanh_fast(pn_s[a] + plrow[a]) * w2_s[a];
        }
        #pragma unroll
        for (int o = 16; o > 0; o >>= 1) s += __shfl_xor_sync(0xffffffffu, s, o);
        if (lane == 0) {
            float lg = s + bias2;
            if (log_mask[b * HL_ + h] == 0) lg = -1e9f;
            logit_s[h] = lg;
        }
    }
    __syncthreads();

    if (warp == 0) {
        float v0 = (lane < HL_)      ? logit_s[lane]      : -3.0e38f;
        float v1 = (lane + 32 < HL_) ? logit_s[lane + 32] : -3.0e38f;
        float mx = fmaxf(v0, v1);
        #pragma unroll
        for (int o = 16; o > 0; o >>= 1) mx = fmaxf(mx, __shfl_xor_sync(0xffffffffu, mx, o));
        float e0 = __expf(v0 - mx), e1 = __expf(v1 - mx);
        float sm = e0 + e1;
        #pragma unroll
        for (int o = 16; o > 0; o >>= 1) sm += __shfl_xor_sync(0xffffffffu, sm, o);
        float inv = 1.f / sm;
        if (lane < HL_)      logit_s[lane]      = e0 * inv;
        if (lane + 32 < HL_) logit_s[lane + 32] = e1 * inv;
    }
    __syncthreads();

    const float* lfb = g_lf + (size_t)b * HL_ * NEWS_;
    float acc0 = 0.f, acc1 = 0.f;
    #pragma unroll 5
    for (int h = 0; h < HL_; h++) {
        float ah = logit_s[h];
        acc0 += ah * lfb[h * NEWS_ + tid];
        if (tid < NEWS_ - ATT_) acc1 += ah * lfb[h * NEWS_ + ATT_ + tid];
    }
    out[(size_t)bn * NEWS_ + tid] = acc0;
    if (tid < NEWS_ - ATT_) out[(size_t)bn * NEWS_ + ATT_ + tid] = acc1;
}

// ---------------------------------------------------------------------------
extern "C" void kernel_launch(void* const* d_in, const int* in_sizes, int n_in,
                              void* d_out, int out_size)
{
    const float* log_vec  = (const float*)d_in[0];
    const int*   log_mask = (const int*)  d_in[1];
    const float* news_vec = (const float*)d_in[2];
    const float* pos_emb  = (const float*)d_in[3];
    const float* W1       = (const float*)d_in[4];
    const float* b1       = (const float*)d_in[5];
    const float* W2       = (const float*)d_in[6];
    const float* b2       = (const float*)d_in[7];
    float* out = (float*)d_out;

    const int NF_TOTAL = B_ * NN_ * NEWS_;       // 1,835,008
    const int LF_TOTAL = B_ * HL_ * NEWS_;       // 1,433,600
    int setup_blocks = (NF_TOTAL + LF_TOTAL + 255) / 256;

    // out layout: [user_log_vecs (B,NN,NEWS) | nf (B,NN,NEWS)]
    setup_kernel<<<setup_blocks, 256>>>(log_vec, news_vec, pos_emb, out + NF_TOTAL);
    cncl_kernel<<<HL_ + 1, 256>>>(pos_emb, W1, b1);
    gemm_kernel<<<dim3(ATT_ / BN, (B_ * NN_) / BM), 256>>>(news_vec, W1, 0,     0);
    gemm_kernel<<<dim3(ATT_ / BN, (B_ * HL_) / BM), 256>>>(log_vec,  W1, NEWS_, 1);
    core_kernel<<<B_ * NN_, 256>>>(log_mask, W2, b2, out);
}

// round 3
// speedup vs baseline: 1.4587x; 1.4587x over previous
#include <cuda_runtime.h>
#include <cuda_bf16.h>
#include <cstdint>

#define B_   64
#define NN_  64
#define HL_  50
#define IN_  384
#define POS_ 64
#define ATT_ 256
#define NEWS_ 448
#define W1COLS_ 896

// Scratch
__device__ float g_pn[B_ * NN_ * ATT_];
__device__ float g_pl[B_ * HL_ * ATT_];
__device__ float g_cn[ATT_];
__device__ float g_cl[HL_ * ATT_];

__device__ __forceinline__ float tanh_fast(float x) {
    float y; asm("tanh.approx.f32 %0, %1;" : "=f"(y) : "f"(x)); return y;
}
__device__ __forceinline__ uint32_t to_tf32(float f) {
    uint32_t r; asm("cvt.rna.tf32.f32 %0, %1;" : "=r"(r) : "f"(f)); return r;
}
__device__ __forceinline__ void mma_tf32(float* c, const uint32_t* a, const uint32_t* b) {
    asm volatile(
        "mma.sync.aligned.m16n8k8.row.col.f32.tf32.tf32.f32 "
        "{%0,%1,%2,%3}, {%4,%5,%6,%7}, {%8,%9}, {%0,%1,%2,%3};"
        : "+f"(c[0]), "+f"(c[1]), "+f"(c[2]), "+f"(c[3])
        : "r"(a[0]), "r"(a[1]), "r"(a[2]), "r"(a[3]), "r"(b[0]), "r"(b[1]));
}

// ---------------------------------------------------------------------------
// Kernel 1: build nf -> out second half
// ---------------------------------------------------------------------------
__global__ __launch_bounds__(256) void setup_kernel(
    const float* __restrict__ news_vec,
    const float* __restrict__ pos_emb,
    float* __restrict__ nf_out)
{
    const int NF_TOTAL = B_ * NN_ * NEWS_;
    int idx = blockIdx.x * 256 + threadIdx.x;
    if (idx < NF_TOTAL) {
        int d = idx % NEWS_;
        int r = idx / NEWS_;
        nf_out[idx] = (d < IN_) ? news_vec[r * IN_ + d] : pos_emb[d - IN_];
    }
}

// ---------------------------------------------------------------------------
// Kernel 2: cn / cl bias folding (exact fp32)
// ---------------------------------------------------------------------------
__global__ __launch_bounds__(256) void cncl_kernel(
    const float* __restrict__ pos_emb,
    const float* __restrict__ W1,
    const float* __restrict__ b1)
{
    int a = threadIdx.x;
    int blk = blockIdx.x;
    if (blk == 0) {
        float s = b1[a];
        const float* w = W1 + a * W1COLS_ + IN_;
        #pragma unroll 8
        for (int p = 0; p < POS_; p++) s += pos_emb[p] * w[p];
        g_cn[a] = s;
    } else {
        int h = blk - 1;
        float s = 0.f;
        const float* w  = W1 + a * W1COLS_ + NEWS_ + IN_;
        const float* pe = pos_emb + (1 + h) * POS_;
        #pragma unroll 8
        for (int p = 0; p < POS_; p++) s += pe[p] * w[p];
        g_cl[h * ATT_ + a] = s;
    }
}

// ---------------------------------------------------------------------------
// Kernel 3: mma.sync tf32 GEMM. C[m,a] = A[m,:384] . W1[a, w_off:+384] + bias
// Block tile 128x128, BK=32, 8 warps (2m x 4n), warp tile 64x32, m16n8k8.
// Grid: 114 blocks = (32 news-tiles + 25 log-tiles) x 2 N-halves.
// ---------------------------------------------------------------------------
#define BK 32
#define LDT 36          // smem row stride (floats): conflict-free for frag loads
#define NKT (IN_ / BK)  // 12

__global__ __launch_bounds__(256) void gemm_mma_kernel(
    const float* __restrict__ news_vec,
    const float* __restrict__ log_vec,
    const float* __restrict__ W1)
{
    __shared__ uint32_t As[128 * LDT];
    __shared__ uint32_t Ws[128 * LDT];

    int tid  = threadIdx.x;
    int wid  = tid >> 5, lane = tid & 31;
    int gid  = lane >> 2, tig = lane & 3;
    int wm   = wid & 1;            // 0..1  (64 rows each)
    int wn   = wid >> 1;           // 0..3  (32 cols each)

    int bx   = blockIdx.x;
    int nh   = bx & 1;
    int tile = bx >> 1;
    int mode, mtile, w_off;
    const float* A;
    if (tile < 32) { mode = 0; mtile = tile;      A = news_vec; w_off = 0; }
    else           { mode = 1; mtile = tile - 32; A = log_vec;  w_off = NEWS_; }
    int n_base = nh * 128;

    // global load mapping: row = p*32 + (tid>>3), col-f4 = tid&7
    int lrow = tid >> 3;           // 0..31
    int lf4  = tid & 7;            // 0..7
    const float* Abase = A  + (size_t)(mtile * 128 + lrow) * IN_ + lf4 * 4;
    const float* Wbase = W1 + (size_t)(n_base + lrow) * W1COLS_ + w_off + lf4 * 4;

    float acc[4][4][4];
    #pragma unroll
    for (int i = 0; i < 4; i++)
        #pragma unroll
        for (int j = 0; j < 4; j++)
            #pragma unroll
            for (int k = 0; k < 4; k++) acc[i][j][k] = 0.f;

    float4 aReg[4], wReg[4];
    #pragma unroll
    for (int p = 0; p < 4; p++) {
        aReg[p] = *(const float4*)(Abase + (size_t)p * 32 * IN_);
        wReg[p] = *(const float4*)(Wbase + (size_t)p * 32 * W1COLS_);
    }

    for (int kt = 0; kt < NKT; kt++) {
        // store current tile to smem (tf32-converted)
        #pragma unroll
        for (int p = 0; p < 4; p++) {
            uint32_t* as = &As[(p * 32 + lrow) * LDT + lf4 * 4];
            as[0] = to_tf32(aReg[p].x); as[1] = to_tf32(aReg[p].y);
            as[2] = to_tf32(aReg[p].z); as[3] = to_tf32(aReg[p].w);
            uint32_t* ws = &Ws[(p * 32 + lrow) * LDT + lf4 * 4];
            ws[0] = to_tf32(wReg[p].x); ws[1] = to_tf32(wReg[p].y);
            ws[2] = to_tf32(wReg[p].z); ws[3] = to_tf32(wReg[p].w);
        }
        __syncthreads();

        // prefetch next tile
        if (kt + 1 < NKT) {
            const float* An = Abase + (kt + 1) * BK;
            const float* Wn = Wbase + (kt + 1) * BK;
            #pragma unroll
            for (int p = 0; p < 4; p++) {
                aReg[p] = *(const float4*)(An + (size_t)p * 32 * IN_);
                wReg[p] = *(const float4*)(Wn + (size_t)p * 32 * W1COLS_);
            }
        }

        // compute: 4 k8-substeps
        #pragma unroll
        for (int kk = 0; kk < BK; kk += 8) {
            uint32_t afr[4][4], bfr[4][2];
            #pragma unroll
            for (int mf = 0; mf < 4; mf++) {
                int r0 = (wm * 64 + mf * 16 + gid) * LDT + kk + tig;
                afr[mf][0] = As[r0];
                afr[mf][1] = As[r0 + 8 * LDT];
                afr[mf][2] = As[r0 + 4];
                afr[mf][3] = As[r0 + 8 * LDT + 4];
            }
            #pragma unroll
            for (int nf = 0; nf < 4; nf++) {
                int c0 = (wn * 32 + nf * 8 + gid) * LDT + kk + tig;
                bfr[nf][0] = Ws[c0];
                bfr[nf][1] = Ws[c0 + 4];
            }
            #pragma unroll
            for (int mf = 0; mf < 4; mf++)
                #pragma unroll
                for (int nf = 0; nf < 4; nf++)
                    mma_tf32(acc[mf][nf], afr[mf], bfr[nf]);
        }
        __syncthreads();
    }

    // epilogue: add bias, store to g_pn / g_pl
    float* outp = (mode == 0) ? g_pn : g_pl;
    #pragma unroll
    for (int mf = 0; mf < 4; mf++) {
        int r0 = mtile * 128 + wm * 64 + mf * 16 + gid;
        int r1 = r0 + 8;
        const float* bias0;
        const float* bias1;
        if (mode == 0) { bias0 = g_cn; bias1 = g_cn; }
        else { bias0 = g_cl + (r0 % HL_) * ATT_; bias1 = g_cl + (r1 % HL_) * ATT_; }
        #pragma unroll
        for (int nf = 0; nf < 4; nf++) {
            int c = n_base + wn * 32 + nf * 8 + 2 * tig;
            float2 v0, v1;
            v0.x = acc[mf][nf][0] + bias0[c];
            v0.y = acc[mf][nf][1] + bias0[c + 1];
            v1.x = acc[mf][nf][2] + bias1[c];
            v1.y = acc[mf][nf][3] + bias1[c + 1];
            *(float2*)(outp + (size_t)r0 * ATT_ + c) = v0;
            *(float2*)(outp + (size_t)r1 * ATT_ + c) = v1;
        }
    }
}

// ---------------------------------------------------------------------------
// Kernel 4: fused tanh-attn core. Block = (b, half of n) -> 32 n's. 512 thr.
// ---------------------------------------------------------------------------
#define CORE_SMEM (50 * 256 * 4 + 1024 + 1024 + 256 + 256)
__global__ __launch_bounds__(512, 1) void core_kernel(
    const float* __restrict__ log_vec,
    const float* __restrict__ pos_emb,
    const int*   __restrict__ log_mask,
    const float* __restrict__ W2,
    const float* __restrict__ b2,
    float* __restrict__ out)
{
    extern __shared__ char dsm[];
    float* pl_s    = (float*)dsm;                       // 50*256
    float* pn_s    = pl_s + 50 * 256;                   // 256
    float* w2_s    = pn_s + 256;                        // 256
    float* logit_s = w2_s + 256;                        // 64
    int*   mask_s  = (int*)(logit_s + 64);              // 64

    int tid  = threadIdx.x;
    int b    = blockIdx.x >> 1;
    int half = blockIdx.x & 1;
    int warp = tid >> 5, lane = tid & 31;

    const float4* plg = (const float4*)(g_pl + (size_t)b * HL_ * ATT_);
    for (int i = tid; i < 50 * 64; i += 512) ((float4*)pl_s)[i] = plg[i];
    if (tid < ATT_) w2_s[tid] = W2[tid];
    if (tid < HL_)  mask_s[tid] = log_mask[b * HL_ + tid];

    float lf_reg[HL_];
    int d = tid;
    if (d < NEWS_) {
        if (d < IN_) {
            const float* lv = log_vec + (size_t)b * HL_ * IN_ + d;
            #pragma unroll
            for (int h = 0; h < HL_; h++) lf_reg[h] = lv[h * IN_];
        } else {
            const float* pe = pos_emb + POS_ + (d - IN_);
            #pragma unroll
            for (int h = 0; h < HL_; h++) lf_reg[h] = pe[h * POS_];
        }
    }
    float bias2 = b2[0];
    __syncthreads();

    for (int i = 0; i < 32; i++) {
        int n  = half * 32 + i;
        int bn = b * NN_ + n;
        if (tid < ATT_) pn_s[tid] = g_pn[(size_t)bn * ATT_ + tid];
        __syncthreads();

        for (int h = warp; h < HL_; h += 16) {
            const float* plrow = pl_s + h * ATT_;
            float s = 0.f;
            #pragma unroll
            for (int j = 0; j < 8; j++) {
                int a = lane + 32 * j;
                s += tanh_fast(pn_s[a] + plrow[a]) * w2_s[a];
            }
            #pragma unroll
            for (int o = 16; o > 0; o >>= 1) s += __shfl_xor_sync(0xffffffffu, s, o);
            if (lane == 0)
                logit_s[h] = (mask_s[h] == 0) ? -1e9f : (s + bias2);
        }
        __syncthreads();

        if (warp == 0) {
            float v0 = (lane < HL_)      ? logit_s[lane]      : -3.0e38f;
            float v1 = (lane + 32 < HL_) ? logit_s[lane + 32] : -3.0e38f;
            float mx = fmaxf(v0, v1);
            #pragma unroll
            for (int o = 16; o > 0; o >>= 1) mx = fmaxf(mx, __shfl_xor_sync(0xffffffffu, mx, o));
            float e0 = __expf(v0 - mx), e1 = __expf(v1 - mx);
            float sm = e0 + e1;
            #pragma unroll
            for (int o = 16; o > 0; o >>= 1) sm += __shfl_xor_sync(0xffffffffu, sm, o);
            float inv = 1.f / sm;
            if (lane < HL_)      logit_s[lane]      = e0 * inv;
            if (lane + 32 < HL_) logit_s[lane + 32] = e1 * inv;
        }
        __syncthreads();

        if (d < NEWS_) {
            float acc = 0.f;
            #pragma unroll
            for (int h = 0; h < HL_; h++) acc += logit_s[h] * lf_reg[h];
            out[(size_t)bn * NEWS_ + d] = acc;
        }
        __syncthreads();
    }
}

// ---------------------------------------------------------------------------
extern "C" void kernel_launch(void* const* d_in, const int* in_sizes, int n_in,
                              void* d_out, int out_size)
{
    const float* log_vec  = (const float*)d_in[0];
    const int*   log_mask = (const int*)  d_in[1];
    const float* news_vec = (const float*)d_in[2];
    const float* pos_emb  = (const float*)d_in[3];
    const float* W1       = (const float*)d_in[4];
    const float* b1       = (const float*)d_in[5];
    const float* W2       = (const float*)d_in[6];
    const float* b2       = (const float*)d_in[7];
    float* out = (float*)d_out;

    const int NF_TOTAL = B_ * NN_ * NEWS_;
    cudaFuncSetAttribute(core_kernel, cudaFuncAttributeMaxDynamicSharedMemorySize, CORE_SMEM);

    setup_kernel<<<(NF_TOTAL + 255) / 256, 256>>>(news_vec, pos_emb, out + NF_TOTAL);
    cncl_kernel<<<HL_ + 1, 256>>>(pos_emb, W1, b1);
    gemm_mma_kernel<<<114, 256>>>(news_vec, log_vec, W1);
    core_kernel<<<B_ * 2, 512, CORE_SMEM>>>(log_vec, pos_emb, log_mask, W2, b2, out);
}